// round 16
// baseline (speedup 1.0000x reference)
#include <cuda_runtime.h>
#include <cstdint>

// MobiusFlow4ND — 4 pairs per warp (8 lanes per pair), 21 warps per block.
// Block = 84 pairs = 4 batch rows; grid = B/4 = 1024.
//
// R15 = R14 resubmitted verbatim (R14 never executed: "container failed twice"
// with no verdict = infra flake; same signature as R12, whose resubmission
// passed). R14 vs R13: the k-loop is restructured from 8 pipelined iterations
// into 4 trips x 2 fully-independent chains (k = gl+16t and gl+16t+8) in one
// branchless block, so ptxas can interleave two complete dependency chains
// per warp (R13 only overlapped the next head with the current tail).
// Per-lane accumulation order is unchanged (gl, gl+8, gl+16, ...).

#define NPER 21
#define PAIRS_PER_BLOCK 84      // 21 warps * 4 groups
#define ROWS_PER_BLOCK 4
#define ROW_F 264               // padded row stride in floats (1056 B; mod 32 = 8)
#define SMEM_FLOATS (PAIRS_PER_BLOCK * ROW_F)
#define SMEM_BYTES  (SMEM_FLOATS * 4 + PAIRS_PER_BLOCK * 4)
#define TWO_PI 6.28318530717958647692f
#define PI_F   3.14159265358979323846f
#define HALF_PI 1.57079632679489661923f

__device__ __forceinline__ void cp16(uint32_t dst, const char* src) {
    asm volatile("cp.async.cg.shared.global [%0], [%1], 16;" :: "r"(dst), "l"(src));
}

// atan2(y,x) mapped to [0, 2pi): q = |atan2| in [0,pi]; result = y>=0 ? q : 2pi-q.
__device__ __forceinline__ float ang02pi(float y, float x) {
    float ax = fabsf(x), ay = fabsf(y);
    float hi = fmaxf(ax, ay);
    float lo = fminf(ax, ay);
    float a  = (hi > 0.0f) ? __fdividef(lo, hi) : 0.0f;
    float s  = a * a;
    // minimax atan on [0,1], max err ~1e-5 rad
    float p = 0.0208351f;
    p = fmaf(p, s, -0.0851330f);
    p = fmaf(p, s,  0.1801410f);
    p = fmaf(p, s, -0.3302995f);
    p = fmaf(p, s,  0.9998660f);
    p = p * a;
    if (ay > ax)  p = HALF_PI - p;
    if (x < 0.0f) p = PI_F - p;          // now p = q in [0, pi]
    return (y >= 0.0f) ? p : TWO_PI - p;
}

__device__ __forceinline__ float softplus_f(float t) {
    return (t > 15.0f) ? t : __logf(1.0f + __expf(t));
}

// permute arrives either as 3 x int32 or 3 x int64 (little-endian words).
__device__ __forceinline__ void decode_perm(const int* pi, int& p0, int& p1, int& p2) {
    int a = pi[0], b = pi[1], c = pi[2];
    bool is32 = (a >= 0 && a < 3) && (b >= 0 && b < 3) && (c >= 0 && c < 3) &&
                (a != b) && (b != c) && (a != c);
    if (is32) { p0 = a; p1 = b; p2 = c; }
    else      { p0 = pi[0]; p1 = pi[2]; p2 = pi[4]; }
}

// One full Mobius k-term: consumes raw (sp, w), updates S/A/G.
__device__ __forceinline__ void mob_iter(
    float spRaw, float w0, float w1, float w2,
    float x0, float x1, float x2,
    float y0, float y1, float y2,
    float r0, float r1, float r2,
    float v0, float v1, float v2,
    float& S, float& A, float& G)
{
    float sp = softplus_f(spRaw);

    // proj = I - y y^T (raw y)
    float d = fmaf(y0, w0, fmaf(y1, w1, y2 * w2));
    w0 = fmaf(-y0, d, w0);
    w1 = fmaf(-y1, d, w1);
    w2 = fmaf(-y2, d, w2);

    // w *= 0.7/(1+|w|); |w| via rsqrt
    float wn2r = fmaf(w0, w0, fmaf(w1, w1, w2 * w2));
    float wn   = (wn2r > 0.0f) ? wn2r * rsqrtf(wn2r) : 0.0f;
    float sc   = __fdividef(0.7f, 1.0f + wn);
    w0 *= sc; w1 *= sc; w2 *= sc;
    float wn2 = sc * sc * wn2r;

    // zw = x - w ; f = (1-|w|^2)/|zw|^2
    float zw0 = x0 - w0, zw1 = x1 - w1, zw2 = x2 - w2;
    float zn2 = fmaf(zw0, zw0, fmaf(zw1, zw1, zw2 * zw2));
    float f   = __fdividef(1.0f - wn2, zn2);

    // h_z = f*zw - w
    float h0 = fmaf(f, zw0, -w0);
    float h1 = fmaf(f, zw1, -w1);
    float h2 = fmaf(f, zw2, -w2);

    float hv = fmaf(h0, v0, fmaf(h1, v1, h2 * v2));
    float hr = fmaf(h0, r0, fmaf(h1, r1, h2 * r2));

    float ang = ang02pi(hv, hr);

    S += sp;
    A = fmaf(sp, ang, A);
    G = fmaf(sp, f, G);   // |dh_dtheta| == f (Householder preserves unit norm)
}

__global__ __launch_bounds__(672, 2)
void mobius_kernel(const float* __restrict__ rot,
                   const float* __restrict__ cond,
                   const int* __restrict__ perm,
                   float* __restrict__ out,
                   long long ldj_off,
                   long long npairs,
                   int B)
{
    extern __shared__ float smem[];
    float* sldj = smem + SMEM_FLOATS;

    const int tid  = threadIdx.x;
    const int lane = tid & 31;
    const int wid  = tid >> 5;           // warp 0..20
    const int g    = lane >> 3;          // group within warp: 0..3
    const int gl   = lane & 7;           // lane within group: 0..7
    const int bp   = wid * 4 + g;        // pair index within block: 0..83

    long long pair = (long long)blockIdx.x * PAIRS_PER_BLOCK + bp;
    const bool active = pair < npairs;
    if (!active) pair = 0;               // clamp; stores guarded

    long long warpPair0 = (long long)blockIdx.x * PAIRS_PER_BLOCK + wid * 4;
    if (warpPair0 > npairs - 4) warpPair0 = npairs - 4;
    const char* warpSrc = (const char*)(cond + warpPair0 * 256);

    // ---- Hoisted single-phase staging: this warp's 4 contiguous rows (4KB).
    uint32_t sbase = (uint32_t)__cvta_generic_to_shared(smem);
    const uint32_t dstB = sbase + (uint32_t)(wid * 4) * 1056u + (uint32_t)lane * 16u;
    const char*    srcB = warpSrc + lane * 16;
    cp16(dstB + 0,    srcB + 0);
    cp16(dstB + 512,  srcB + 512);
    cp16(dstB + 1056, srcB + 1024);
    cp16(dstB + 1568, srcB + 1536);
    cp16(dstB + 2112, srcB + 2048);
    cp16(dstB + 2624, srcB + 2560);
    cp16(dstB + 3168, srcB + 3072);
    cp16(dstB + 3680, srcB + 3584);
    asm volatile("cp.async.commit_group;");

    int p0, p1, p2;
    decode_perm(perm, p0, p1, p2);

    // ---- Frame computation overlaps the cp.async flight ----
    const float* rp = rot + pair * 9;
    float x0 = __ldg(rp + 0 * 3 + p0), x1 = __ldg(rp + 1 * 3 + p0), x2 = __ldg(rp + 2 * 3 + p0);
    float y0 = __ldg(rp + 0 * 3 + p1), y1 = __ldg(rp + 1 * 3 + p1), y2 = __ldg(rp + 2 * 3 + p1);

    float inx = rsqrtf(fmaf(x0, x0, fmaf(x1, x1, x2 * x2)));
    float r0 = -x0 * inx, r1 = -x1 * inx, r2 = -x2 * inx;
    float v0 = fmaf(y1, r2, -y2 * r1);
    float v1 = fmaf(y2, r0, -y0 * r2);
    float v2 = fmaf(y0, r1, -y1 * r0);
    float inv = rsqrtf(fmaf(v0, v0, fmaf(v1, v1, v2 * v2)));
    v0 *= inv; v1 *= inv; v2 *= inv;

    asm volatile("cp.async.wait_group 0;");
    __syncwarp();

    const float* myrow = smem + bp * ROW_F;

    float S = 0.0f, A = 0.0f, G = 0.0f;

    // ---- 4 trips x 2 independent chains (kA = gl+16t, kB = kA+8) ----
    #pragma unroll
    for (int t = 0; t < 4; ++t) {
        const int kA = gl + t * 16;
        const int kB = kA + 8;

        float spA = myrow[kA];
        float wA0 = myrow[64 + 3 * kA + 0];
        float wA1 = myrow[64 + 3 * kA + 1];
        float wA2 = myrow[64 + 3 * kA + 2];

        float spB = myrow[kB];
        float wB0 = myrow[64 + 3 * kB + 0];
        float wB1 = myrow[64 + 3 * kB + 1];
        float wB2 = myrow[64 + 3 * kB + 2];

        mob_iter(spA, wA0, wA1, wA2, x0, x1, x2, y0, y1, y2,
                 r0, r1, r2, v0, v1, v2, S, A, G);
        mob_iter(spB, wB0, wB1, wB2, x0, x1, x2, y0, y1, y2,
                 r0, r1, r2, v0, v1, v2, S, A, G);
    }

    // reduce S, A, G over the 8-lane group
    #pragma unroll
    for (int off = 4; off; off >>= 1) {
        S += __shfl_xor_sync(0xFFFFFFFFu, S, off);
        A += __shfl_xor_sync(0xFFFFFFFFu, A, off);
        G += __shfl_xor_sync(0xFFFFFFFFu, G, off);
    }

    float invS = __fdividef(1.0f, S);
    float ang  = A * invS;
    float sA, cA;
    __sincosf(ang, &sA, &cA);

    float tx0 = fmaf(r0, cA, v0 * sA);
    float tx1 = fmaf(r1, cA, v1 * sA);
    float tx2 = fmaf(r2, cA, v2 * sA);

    float ldj = __logf(G * invS);

    // tz = cross(tx, y) if (p1-p0==1 || p1-p0==-2) else cross(y, tx); normalized
    int dp = p1 - p0;
    bool fwd = (dp == 1) || (dp == -2);
    float a0, a1, a2, b0, b1, b2;
    if (fwd) { a0 = tx0; a1 = tx1; a2 = tx2; b0 = y0;  b1 = y1;  b2 = y2;  }
    else     { a0 = y0;  a1 = y1;  a2 = y2;  b0 = tx0; b1 = tx1; b2 = tx2; }
    float tz0 = fmaf(a1, b2, -a2 * b1);
    float tz1 = fmaf(a2, b0, -a0 * b2);
    float tz2 = fmaf(a0, b1, -a1 * b0);
    float itz = rsqrtf(fmaf(tz0, tz0, fmaf(tz1, tz1, tz2 * tz2)));
    tz0 *= itz; tz1 *= itz; tz2 *= itz;

    // Group leader stores the 3x3 (9 STG issues serve 4 pairs each).
    if (gl == 0 && active) {
        float* op = out + pair * 9;
        op[0 * 3 + p0] = tx0; op[1 * 3 + p0] = tx1; op[2 * 3 + p0] = tx2;
        op[0 * 3 + p1] = y0;  op[1 * 3 + p1] = y1;  op[2 * 3 + p1] = y2;
        op[0 * 3 + p2] = tz0; op[1 * 3 + p2] = tz1; op[2 * 3 + p2] = tz2;
    }

    // Deterministic ldj row-sums: 84 pairs = 4 rows per block.
    if (gl == 0) sldj[bp] = active ? ldj : 0.0f;
    __syncthreads();
    if (tid < ROWS_PER_BLOCK) {
        long long row = (long long)blockIdx.x * ROWS_PER_BLOCK + tid;
        if (row < B) {
            float s = 0.0f;
            #pragma unroll
            for (int i = 0; i < NPER; ++i) s += sldj[tid * NPER + i];
            out[ldj_off + row] = s;
        }
    }
}

extern "C" void kernel_launch(void* const* d_in, const int* in_sizes, int n_in,
                              void* d_out, int out_size) {
    const float* rot  = (const float*)d_in[0];
    const float* cond = (const float*)d_in[1];
    const int*   perm = (const int*)d_in[2];
    float* out = (float*)d_out;

    const long long rot_elems = in_sizes[0];          // B*N*9
    const long long npairs    = rot_elems / 9;        // B*N
    const int B = (int)(npairs / NPER);               // 4096
    const long long ldj_off = rot_elems;              // trotation first, then ldj[B]

    // One-time, pre-capture (first call is the harness's correctness run).
    static bool attr_set = false;
    if (!attr_set) {
        cudaFuncSetAttribute(mobius_kernel,
                             cudaFuncAttributeMaxDynamicSharedMemorySize,
                             SMEM_BYTES);
        attr_set = true;
    }

    const int grid = (int)((npairs + PAIRS_PER_BLOCK - 1) / PAIRS_PER_BLOCK);
    mobius_kernel<<<grid, 672, SMEM_BYTES>>>(rot, cond, perm, out, ldj_off, npairs, B);
}